// round 16
// baseline (speedup 1.0000x reference)
#include <cuda_runtime.h>
#include <cuda_fp16.h>
#include <math.h>
#include <stdint.h>

// Problem dims
#define BB   8
#define NNN  200
#define NDD  128
#define HHH  256
#define FFF  1024
#define LLL  3
#define NH_  8
#define DH_  32
#define ROWS (BB*NNN)          // 1600
#define SLAB (ROWS*HHH)        // 409600 floats
#define QKVOFF ((size_t)ROWS*768)   // qkv split-K partial stride (floats)

// ---------------- scratch (device globals; no allocation allowed) -----------
__device__ float g_x   [ROWS*HHH];
__device__ float g_qkv [2*ROWS*3*HHH];   // 2 split-K partial slabs
__device__ float g_tmp [ROWS*FFF];       // 4 slabs of ROWS*HHH
__device__ float g_o   [ROWS*HHH];
__device__ float g_p4  [4*SLAB];         // split-K=4 GEMM partials
__device__ float g_temb[BB*HHH];
__device__ float g_u   [HHH];
__device__ float g_vv  [HHH];

// ---------------- fp16 helpers ----------------------------------------------
__device__ __forceinline__ uint32_t pack_h2(float a, float b) {
    __half2 h = __floats2half2_rn(a, b);
    return *(uint32_t*)&h;
}
__device__ __forceinline__ void mma_f16(float* c, uint32_t a0, uint32_t a1,
                                        uint32_t a2, uint32_t a3,
                                        uint32_t b0, uint32_t b1) {
    asm volatile(
        "mma.sync.aligned.m16n8k16.row.col.f32.f16.f16.f32 "
        "{%0,%1,%2,%3}, {%4,%5,%6,%7}, {%8,%9}, {%0,%1,%2,%3};"
        : "+f"(c[0]), "+f"(c[1]), "+f"(c[2]), "+f"(c[3])
        : "r"(a0), "r"(a1), "r"(a2), "r"(a3), "r"(b0), "r"(b1));
}

// ------- fp16 GEMM, CTA 64x64, 4 warps of 32x32, BK=32, double-buffered -----
// gridDim.z = split-K; partial z -> C + z*M*Nc (no bias when nz>1).
// mode: 0=+bias, 1=+bias,relu, 2=+bias+temb[row/200],
//       3=dual-W head (bx>>2 selects wa/wb, output slab pair offset)
__global__ void __launch_bounds__(128, 5)
tgemm(const float* __restrict__ A, const float* __restrict__ W,
      const float* __restrict__ bias, const float* __restrict__ temb,
      float* __restrict__ C, int M, int K, int Nc, int mode)
{
    __shared__ __align__(16) uint32_t As[2][64][20];   // 16 u32 = 32 halves/row
    __shared__ __align__(16) uint32_t Bs[2][16][72];   // row=kpair, col=n

    const int tid = threadIdx.x;
    int bx = blockIdx.x;
    const int by = blockIdx.y;
    const int z = blockIdx.z, nz = gridDim.z;
    const int kLen = K / nz;
    const int kstart = z * kLen;

    if (mode == 3) {
        int sel = bx >> 2;
        bx &= 3;
        W += (size_t)sel * HHH * HHH;
        C += (size_t)sel * 2 * M * Nc;   // xa slabs 0,1 ; xb slabs 2,3
    }
    C += (size_t)z * M * Nc;

    const int wid  = tid >> 5, lane = tid & 31;
    const int l4   = lane >> 2, lk = lane & 3;
    const int m0   = (wid >> 1) * 32;     // warp row base (0,32)
    const int n0   = (wid & 1) * 32;      // warp col base (0,32)

    // A staging: row ar, u32 cols ak..ak+7 (k offsets ak*2 .. ak*2+15)
    const int ar = tid >> 1;              // 0..63
    const int ak = (tid & 1) * 8;         // 0 or 8 (k 0 or 16)
    // B staging: kpair rows bk,bk+8, n offset bn
    const int bk = tid >> 4;              // 0..7
    const int bn = (tid & 15) * 4;        // 0..60

    const float* Aptr = A + (size_t)(by*64 + ar)*K + kstart + ak*2;
    const float* Wptr = W + (size_t)kstart*Nc + bx*64 + bn;

    // ---- stage tile 0 ----
    {
        float4 a0v = *(const float4*)(Aptr);
        float4 a1v = *(const float4*)(Aptr + 4);
        float4 a2v = *(const float4*)(Aptr + 8);
        float4 a3v = *(const float4*)(Aptr + 12);
        uint4 pa;
        pa.x = pack_h2(a0v.x, a0v.y); pa.y = pack_h2(a0v.z, a0v.w);
        pa.z = pack_h2(a1v.x, a1v.y); pa.w = pack_h2(a1v.z, a1v.w);
        *(uint4*)&As[0][ar][ak] = pa;
        pa.x = pack_h2(a2v.x, a2v.y); pa.y = pack_h2(a2v.z, a2v.w);
        pa.z = pack_h2(a3v.x, a3v.y); pa.w = pack_h2(a3v.z, a3v.w);
        *(uint4*)&As[0][ar][ak + 4] = pa;
#pragma unroll
        for (int cchunk = 0; cchunk < 2; cchunk++) {
            int kp = bk + cchunk*8;
            const float* w0 = Wptr + (size_t)(2*kp)*Nc;
            float4 x0 = *(const float4*)(w0);
            float4 x1 = *(const float4*)(w0 + Nc);
            uint4 pb;
            pb.x = pack_h2(x0.x, x1.x); pb.y = pack_h2(x0.y, x1.y);
            pb.z = pack_h2(x0.z, x1.z); pb.w = pack_h2(x0.w, x1.w);
            *(uint4*)&Bs[0][kp][bn] = pb;
        }
    }
    __syncthreads();

    float c[2][4][4];
#pragma unroll
    for (int t = 0; t < 2; t++)
#pragma unroll
        for (int f = 0; f < 4; f++)
#pragma unroll
            for (int i = 0; i < 4; i++) c[t][f][i] = 0.f;

    int cur = 0;
#pragma unroll 1
    for (int k0 = 32; k0 < kLen; k0 += 32) {
        // prefetch next tile to registers
        float4 a0v = *(const float4*)(Aptr + k0);
        float4 a1v = *(const float4*)(Aptr + k0 + 4);
        float4 a2v = *(const float4*)(Aptr + k0 + 8);
        float4 a3v = *(const float4*)(Aptr + k0 + 12);
        float4 x0a = *(const float4*)(Wptr + (size_t)(k0 + 2*bk    )*Nc);
        float4 x1a = *(const float4*)(Wptr + (size_t)(k0 + 2*bk + 1)*Nc);
        float4 x0b = *(const float4*)(Wptr + (size_t)(k0 + 2*bk + 16)*Nc);
        float4 x1b = *(const float4*)(Wptr + (size_t)(k0 + 2*bk + 17)*Nc);
        // compute current tile: 2 k16 steps
#pragma unroll
        for (int s = 0; s < 2; s++) {
            const int s8 = s * 8;
            uint32_t a[2][4];
#pragma unroll
            for (int t = 0; t < 2; t++) {
                const int mt = m0 + t*16;
                a[t][0] = As[cur][mt + l4    ][s8 + lk    ];
                a[t][1] = As[cur][mt + 8 + l4][s8 + lk    ];
                a[t][2] = As[cur][mt + l4    ][s8 + lk + 4];
                a[t][3] = As[cur][mt + 8 + l4][s8 + lk + 4];
            }
#pragma unroll
            for (int f = 0; f < 4; f++) {
                uint32_t b0 = Bs[cur][s8 + lk    ][n0 + f*8 + l4];
                uint32_t b1 = Bs[cur][s8 + lk + 4][n0 + f*8 + l4];
                mma_f16(c[0][f], a[0][0], a[0][1], a[0][2], a[0][3], b0, b1);
                mma_f16(c[1][f], a[1][0], a[1][1], a[1][2], a[1][3], b0, b1);
            }
        }
        int nb = cur ^ 1;
        {
            uint4 pa;
            pa.x = pack_h2(a0v.x, a0v.y); pa.y = pack_h2(a0v.z, a0v.w);
            pa.z = pack_h2(a1v.x, a1v.y); pa.w = pack_h2(a1v.z, a1v.w);
            *(uint4*)&As[nb][ar][ak] = pa;
            pa.x = pack_h2(a2v.x, a2v.y); pa.y = pack_h2(a2v.z, a2v.w);
            pa.z = pack_h2(a3v.x, a3v.y); pa.w = pack_h2(a3v.z, a3v.w);
            *(uint4*)&As[nb][ar][ak + 4] = pa;
            uint4 pb;
            pb.x = pack_h2(x0a.x, x1a.x); pb.y = pack_h2(x0a.y, x1a.y);
            pb.z = pack_h2(x0a.z, x1a.z); pb.w = pack_h2(x0a.w, x1a.w);
            *(uint4*)&Bs[nb][bk][bn] = pb;
            pb.x = pack_h2(x0b.x, x1b.x); pb.y = pack_h2(x0b.y, x1b.y);
            pb.z = pack_h2(x0b.z, x1b.z); pb.w = pack_h2(x0b.w, x1b.w);
            *(uint4*)&Bs[nb][bk + 8][bn] = pb;
        }
        __syncthreads();
        cur = nb;
    }
    // ---- last tile ----
#pragma unroll
    for (int s = 0; s < 2; s++) {
        const int s8 = s * 8;
        uint32_t a[2][4];
#pragma unroll
        for (int t = 0; t < 2; t++) {
            const int mt = m0 + t*16;
            a[t][0] = As[cur][mt + l4    ][s8 + lk    ];
            a[t][1] = As[cur][mt + 8 + l4][s8 + lk    ];
            a[t][2] = As[cur][mt + l4    ][s8 + lk + 4];
            a[t][3] = As[cur][mt + 8 + l4][s8 + lk + 4];
        }
#pragma unroll
        for (int f = 0; f < 4; f++) {
            uint32_t b0 = Bs[cur][s8 + lk    ][n0 + f*8 + l4];
            uint32_t b1 = Bs[cur][s8 + lk + 4][n0 + f*8 + l4];
            mma_f16(c[0][f], a[0][0], a[0][1], a[0][2], a[0][3], b0, b1);
            mma_f16(c[1][f], a[1][0], a[1][1], a[1][2], a[1][3], b0, b1);
        }
    }

    // epilogue: warp rows m0+16t+l4(+8), cols n0+f*8+lk*2 (+1)
#pragma unroll
    for (int t = 0; t < 2; t++) {
#pragma unroll
        for (int f = 0; f < 4; f++) {
            const int col = bx*64 + n0 + f*8 + lk*2;
            float bx0 = 0.f, bx1 = 0.f;
            if (nz == 1 && bias) {
                float2 bv = *(const float2*)(bias + col);
                bx0 = bv.x; bx1 = bv.y;
            }
#pragma unroll
            for (int hh = 0; hh < 2; hh++) {
                const int row = by*64 + m0 + t*16 + l4 + hh*8;
                float v0 = c[t][f][hh*2+0] + bx0;
                float v1 = c[t][f][hh*2+1] + bx1;
                if (mode == 1) { v0 = fmaxf(v0, 0.f); v1 = fmaxf(v1, 0.f); }
                else if (mode == 2) {
                    int b = row / NNN;
                    float2 tv = *(const float2*)(temb + b*HHH + col);
                    v0 += tv.x; v1 += tv.y;
                }
                *(float2*)(C + (size_t)row*Nc + col) = make_float2(v0, v1);
            }
        }
    }
}

// ---------------- t embedding -----------------------------------------------
__global__ void temb_kernel(const float* __restrict__ t, const float* __restrict__ tw1,
                            const float* __restrict__ tb1, const float* __restrict__ tw2,
                            const float* __restrict__ tb2, float* __restrict__ temb)
{
    __shared__ float s[HHH];
    int b = blockIdx.x, h = threadIdx.x;
    float pre = t[b]*tw1[h] + tb1[h];
    s[h] = pre / (1.f + __expf(-pre));
    __syncthreads();
    float acc = tb2[h];
    for (int c = 0; c < HHH; c++) acc = fmaf(s[c], tw2[c*HHH + h], acc);
    temb[b*HHH + h] = acc;
}

// ---------------- fp16 tensor-core attention, warp-split keys ----------------
// grid (64 bh, 4 qtile of 64), 256 threads / 8 warps.
// qkv arrives as TWO split-K partial slabs (stride QKVOFF); staging sums them
// and adds qkv_b -- fusing the qkv combine for free.
// Warp w: m-tile (w&3)*16, key-half w>>2. S = Q@K^T via m16n8k16 f16; exp in
// regs; S C-frag == P A-frag -> O=P@V with no smem P. Upper warp group's
// partials combine via smem. No-max softmax. Padded keys 200..207 zeroed.
__global__ void __launch_bounds__(256, 2)
attn_mma_kernel(const float* __restrict__ qkv, const float* __restrict__ qb,
                float* __restrict__ o)
{
    __shared__ uint32_t Qs[64][20];    // 32 halves/row = 16 u32 + pad
    __shared__ uint32_t Ksm[208][20];
    __shared__ uint32_t Vt[32][108];   // transposed: [dim][key-pairs]
    __shared__ float cbuf[4][32][18];  // partial combine: oacc[16], rs0, rs2

    const int bh = blockIdx.x;
    const int b = bh >> 3, h = bh & 7;
    const int qt = blockIdx.y;
    const int tid = threadIdx.x;
    const int w = tid >> 5, lane = tid & 31;
    const int l4 = lane >> 2, lk = lane & 3;
    const int w16 = (w & 3) * 16;
    const int kh = w >> 2;

    // Q tile: sum partials + bias, scale, fp16, zero-padded rows
    for (int idx = tid; idx < 64*8; idx += 256) {
        int r = idx >> 3, g4 = idx & 7;
        int i = qt*64 + r;
        float4 v = make_float4(0.f, 0.f, 0.f, 0.f);
        if (i < NNN) {
            const float* p = qkv + (size_t)(b*NNN + i)*768 + h*32 + g4*4;
            float4 v0 = *(const float4*)p;
            float4 v1 = *(const float4*)(p + QKVOFF);
            float4 bb = *(const float4*)(qb + h*32 + g4*4);
            v = make_float4(v0.x+v1.x+bb.x, v0.y+v1.y+bb.y,
                            v0.z+v1.z+bb.z, v0.w+v1.w+bb.w);
        }
        const float sc = 0.17677669529663687f;  // 1/sqrt(32)
        Qs[r][g4*2    ] = pack_h2(v.x*sc, v.y*sc);
        Qs[r][g4*2 + 1] = pack_h2(v.z*sc, v.w*sc);
    }
    // K: sum partials + bias, zero rows >= 200
    for (int idx = tid; idx < 208*8; idx += 256) {
        int j = idx >> 3, g4 = idx & 7;
        float4 v = make_float4(0.f, 0.f, 0.f, 0.f);
        if (j < NNN) {
            const float* p = qkv + (size_t)(b*NNN + j)*768 + h*32 + 256 + g4*4;
            float4 v0 = *(const float4*)p;
            float4 v1 = *(const float4*)(p + QKVOFF);
            float4 bb = *(const float4*)(qb + 256 + h*32 + g4*4);
            v = make_float4(v0.x+v1.x+bb.x, v0.y+v1.y+bb.y,
                            v0.z+v1.z+bb.z, v0.w+v1.w+bb.w);
        }
        Ksm[j][g4*2    ] = pack_h2(v.x, v.y);
        Ksm[j][g4*2 + 1] = pack_h2(v.z, v.w);
    }
    // V transposed: sum partials + bias, zero rows >= 200
    for (int idx = tid; idx < 208*8; idx += 256) {
        int j = idx >> 3, g4 = idx & 7;
        float4 v = make_float4(0.f, 0.f, 0.f, 0.f);
        if (j < NNN) {
            const float* p = qkv + (size_t)(b*NNN + j)*768 + h*32 + 512 + g4*4;
            float4 v0 = *(const float4*)p;
            float4 v1 = *(const float4*)(p + QKVOFF);
            float4 bb = *(const float4*)(qb + 512 + h*32 + g4*4);
            v = make_float4(v0.x+v1.x+bb.x, v0.y+v1.y+bb.y,
                            v0.z+v1.z+bb.z, v0.w+v1.w+bb.w);
        }
        __half* r0 = (__half*)&Vt[g4*4    ][0];
        __half* r1 = (__half*)&Vt[g4*4 + 1][0];
        __half* r2 = (__half*)&Vt[g4*4 + 2][0];
        __half* r3 = (__half*)&Vt[g4*4 + 3][0];
        r0[j] = __float2half_rn(v.x);
        r1[j] = __float2half_rn(v.y);
        r2[j] = __float2half_rn(v.z);
        r3[j] = __float2half_rn(v.w);
    }
    __syncthreads();

    // Q fragments (2 k-steps of 16 halves), register-resident
    uint32_t qa[2][4];
#pragma unroll
    for (int s = 0; s < 2; s++) {
        const int o8 = s*8;
        qa[s][0] = Qs[w16 + l4    ][o8 + lk    ];
        qa[s][1] = Qs[w16 + 8 + l4][o8 + lk    ];
        qa[s][2] = Qs[w16 + l4    ][o8 + lk + 4];
        qa[s][3] = Qs[w16 + 8 + l4][o8 + lk + 4];
    }

    float oacc[4][4];
#pragma unroll
    for (int f = 0; f < 4; f++)
#pragma unroll
        for (int i = 0; i < 4; i++) oacc[f][i] = 0.f;
    float rs0 = 0.f, rs2 = 0.f;

    const int fbeg = kh ? 7 : 0;
    const int fend = kh ? 13 : 7;
#pragma unroll 1
    for (int f = fbeg; f < fend; f++) {     // key blocks of 16
        const int klo = 16*f + l4;
        float clo[4] = {0.f, 0.f, 0.f, 0.f};
        float chi[4] = {0.f, 0.f, 0.f, 0.f};
#pragma unroll
        for (int s = 0; s < 2; s++) {
            const int o8 = s*8;
            uint32_t b0 = Ksm[klo    ][o8 + lk];
            uint32_t b1 = Ksm[klo    ][o8 + lk + 4];
            mma_f16(clo, qa[s][0], qa[s][1], qa[s][2], qa[s][3], b0, b1);
            uint32_t c0 = Ksm[klo + 8][o8 + lk];
            uint32_t c1 = Ksm[klo + 8][o8 + lk + 4];
            mma_f16(chi, qa[s][0], qa[s][1], qa[s][2], qa[s][3], c0, c1);
        }
        float p0 = __expf(clo[0]), p1 = __expf(clo[1]);
        float p2 = __expf(clo[2]), p3 = __expf(clo[3]);
        float p4, p5, p6, p7;
        if (f == 12) { p4 = p5 = p6 = p7 = 0.f; }   // keys 200..207 padded
        else {
            p4 = __expf(chi[0]); p5 = __expf(chi[1]);
            p6 = __expf(chi[2]); p7 = __expf(chi[3]);
        }
        // row sums across the quad (lanes sharing l4)
        float s01 = (p0 + p1) + (p4 + p5);
        float s23 = (p2 + p3) + (p6 + p7);
        s01 += __shfl_xor_sync(0xffffffffu, s01, 1);
        s01 += __shfl_xor_sync(0xffffffffu, s01, 2);
        s23 += __shfl_xor_sync(0xffffffffu, s23, 1);
        s23 += __shfl_xor_sync(0xffffffffu, s23, 2);
        rs0 += s01; rs2 += s23;
        // P fragment = packed exps (C-frag layout == A-frag layout)
        uint32_t a0 = pack_h2(p0, p1);
        uint32_t a1 = pack_h2(p2, p3);
        uint32_t a2 = pack_h2(p4, p5);
        uint32_t a3 = pack_h2(p6, p7);
#pragma unroll
        for (int f2 = 0; f2 < 4; f2++) {
            uint32_t b0 = Vt[f2*8 + l4][8*f + lk    ];
            uint32_t b1 = Vt[f2*8 + l4][8*f + lk + 4];
            mma_f16(oacc[f2], a0, a1, a2, a3, b0, b1);
        }
    }

    // upper warp group publishes partials
    if (w >= 4) {
        float* dst = &cbuf[w - 4][lane][0];
#pragma unroll
        for (int f2 = 0; f2 < 4; f2++)
#pragma unroll
            for (int i = 0; i < 4; i++) dst[f2*4 + i] = oacc[f2][i];
        dst[16] = rs0; dst[17] = rs2;
    }
    __syncthreads();
    if (w < 4) {
        const float* src = &cbuf[w][lane][0];
#pragma unroll
        for (int f2 = 0; f2 < 4; f2++)
#pragma unroll
            for (int i = 0; i < 4; i++) oacc[f2][i] += src[f2*4 + i];
        rs0 += src[16]; rs2 += src[17];

        const float inv0 = 1.f / rs0;
        const float inv2 = 1.f / rs2;
        const int i0 = qt*64 + w16 + l4;
        const int i2 = i0 + 8;
#pragma unroll
        for (int f2 = 0; f2 < 4; f2++) {
            const int col = h*32 + f2*8 + 2*lk;
            if (i0 < NNN)
                *(float2*)(o + (size_t)(b*NNN + i0)*HHH + col) =
                    make_float2(oacc[f2][0]*inv0, oacc[f2][1]*inv0);
            if (i2 < NNN)
                *(float2*)(o + (size_t)(b*NNN + i2)*HHH + col) =
                    make_float2(oacc[f2][2]*inv2, oacc[f2][3]*inv2);
        }
    }
}

// -------- LN(x + p0..p3 + bias) in place: merges split-K=4 partials ---------
__global__ void ln_add4_kernel(float* __restrict__ x, const float* __restrict__ p,
                               const float* __restrict__ bias,
                               const float* __restrict__ g, const float* __restrict__ b)
{
    int row = blockIdx.x, c = threadIdx.x;
    size_t idx = (size_t)row*HHH + c;
    float v = x[idx] + (p[idx] + p[SLAB + idx]) + (p[2*(size_t)SLAB + idx] + p[3*(size_t)SLAB + idx]) + bias[c];
    float s1 = v, s2 = v*v;
#pragma unroll
    for (int o = 16; o; o >>= 1) {
        s1 += __shfl_xor_sync(0xffffffffu, s1, o);
        s2 += __shfl_xor_sync(0xffffffffu, s2, o);
    }
    __shared__ float a1[8], a2[8];
    int w = c >> 5, lane = c & 31;
    if (lane == 0) { a1[w] = s1; a2[w] = s2; }
    __syncthreads();
    float t1 = 0.f, t2 = 0.f;
#pragma unroll
    for (int k = 0; k < 8; k++) { t1 += a1[k]; t2 += a2[k]; }
    float mean = t1 * (1.f/256.f);
    float var  = t2 * (1.f/256.f) - mean*mean;
    float inv  = rsqrtf(var + 1e-5f);
    x[idx] = (v - mean)*inv*g[c] + b[c];
}

// ---------------- head precompute: u = ew @ wc, v = eb @ wc + ob1 ----------
__global__ void head_prep_kernel(const float* __restrict__ ew, const float* __restrict__ eb,
                                 const float* __restrict__ ow1, const float* __restrict__ ob1,
                                 float* __restrict__ u, float* __restrict__ v)
{
    int d = threadIdx.x;
    const float* wc = ow1 + 512*HHH;
    float su = 0.f, sv = 0.f;
    for (int c = 0; c < HHH; c++) {
        float w = wc[c*HHH + d];
        su = fmaf(ew[c], w, su);
        sv = fmaf(eb[c], w, sv);
    }
    u[d] = su;
    v[d] = sv + ob1[d];
}

// ---------------- pairwise head ---------------------------------------------
__global__ void head_kernel(const float* __restrict__ xa0, const float* __restrict__ xa1,
                            const float* __restrict__ xb0, const float* __restrict__ xb1,
                            const float* __restrict__ xt, const float* __restrict__ u,
                            const float* __restrict__ v, const float* __restrict__ ow2,
                            const float* __restrict__ ob2, float* __restrict__ out)
{
    __shared__ float xa_s[8][257];
    __shared__ float xb_s[32][257];
    __shared__ float us[HHH];
    __shared__ float2 w2s[HHH];
    const int b = blockIdx.y;
    const int i0 = blockIdx.x * 8;
    const int tid = threadIdx.x;
    const int ii = tid >> 5, jj = tid & 31;

    for (int idx = tid; idx < 8*HHH; idx += 256) {
        int r = idx >> 8, c = idx & 255;
        size_t g = (size_t)(b*NNN + i0 + r)*HHH + c;
        xa_s[r][c] = xa0[g] + xa1[g] + v[c];
    }
    us[tid] = u[tid];
    w2s[tid] = make_float2(ow2[tid*2], ow2[tid*2 + 1]);
    const float obv0 = ob2[0], obv1 = ob2[1];

    for (int j0 = 0; j0 < NNN; j0 += 32) {
        __syncthreads();
        for (int idx = tid; idx < 32*HHH; idx += 256) {
            int r = idx >> 8, c = idx & 255;
            if (j0 + r < NNN) {
                size_t g = (size_t)(b*NNN + j0 + r)*HHH + c;
                xb_s[r][c] = xb0[g] + xb1[g];
            }
        }
        __syncthreads();
        int i = i0 + ii, j = j0 + jj;
        if (j < NNN) {
            float xtv = xt[(size_t)(b*NNN + i)*NNN + j];
            float a0 = 0.f, a1 = 0.f;
#pragma unroll 4
            for (int c = 0; c < HHH; c++) {
                float pre = xa_s[ii][c] + fmaf(xtv, us[c], xb_s[jj][c]);
                float sv2 = __fdividef(pre, 1.f + __expf(-pre));
                float2 w = w2s[c];
                a0 = fmaf(sv2, w.x, a0);
                a1 = fmaf(sv2, w.y, a1);
            }
            ((float2*)out)[(size_t)(b*NNN + i)*NNN + j] = make_float2(a0 + obv0, a1 + obv1);
        }
    }
}

// ---------------- host orchestration ----------------------------------------
extern "C" void kernel_launch(void* const* d_in, const int* in_sizes, int n_in,
                              void* d_out, int out_size)
{
    const float* h_in  = (const float*)d_in[0];
    const float* xt    = (const float*)d_in[1];
    const float* t     = (const float*)d_in[2];
    const float* tw1   = (const float*)d_in[3];
    const float* tb1   = (const float*)d_in[4];
    const float* tw2   = (const float*)d_in[5];
    const float* tb2   = (const float*)d_in[6];
    const float* ew    = (const float*)d_in[7];
    const float* eb    = (const float*)d_in[8];
    const float* pw    = (const float*)d_in[9];
    const float* pb    = (const float*)d_in[10];
    const float* qkv_w = (const float*)d_in[11];
    const float* qkv_b = (const float*)d_in[12];
    const float* ao_w  = (const float*)d_in[13];
    const float* ao_b  = (const float*)d_in[14];
    const float* ln1_g = (const float*)d_in[15];
    const float* ln1_b = (const float*)d_in[16];
    const float* f1_w  = (const float*)d_in[17];
    const float* f1_b  = (const float*)d_in[18];
    const float* f2_w  = (const float*)d_in[19];
    const float* f2_b  = (const float*)d_in[20];
    const float* ln2_g = (const float*)d_in[21];
    const float* ln2_b = (const float*)d_in[22];
    const float* ow1   = (const float*)d_in[23];
    const float* ob1   = (const float*)d_in[24];
    const float* ow2   = (const float*)d_in[25];
    const float* ob2   = (const float*)d_in[26];
    float* out = (float*)d_out;

    float *x, *qkvb, *tmpb, *ob, *p4, *temb, *u, *vv;
    cudaGetSymbolAddress((void**)&x,    g_x);
    cudaGetSymbolAddress((void**)&qkvb, g_qkv);
    cudaGetSymbolAddress((void**)&tmpb, g_tmp);
    cudaGetSymbolAddress((void**)&ob,   g_o);
    cudaGetSymbolAddress((void**)&p4,   g_p4);
    cudaGetSymbolAddress((void**)&temb, g_temb);
    cudaGetSymbolAddress((void**)&u,    g_u);
    cudaGetSymbolAddress((void**)&vv,   g_vv);

    temb_kernel<<<BB, HHH>>>(t, tw1, tb1, tw2, tb2, temb);
    tgemm<<<dim3(HHH/64, ROWS/64, 1), 128>>>(h_in, pw, pb, temb, x, ROWS, NDD, HHH, 2);

    for (int l = 0; l < LLL; l++) {
        const float* qw = qkv_w + (size_t)l*HHH*3*HHH;
        const float* qb = qkv_b + l*3*HHH;
        const float* aw = ao_w + (size_t)l*HHH*HHH;
        const float* ab = ao_b + l*HHH;
        const float* w1 = f1_w + (size_t)l*HHH*FFF;
        const float* b1 = f1_b + l*FFF;
        const float* w2 = f2_w + (size_t)l*FFF*HHH;
        const float* b2 = f2_b + l*HHH;

        // qkv split-K=2 (600 CTAs); attention fuses partial-sum + bias
        tgemm<<<dim3(3*HHH/64, ROWS/64, 2), 128>>>(x, qw, nullptr, nullptr, qkvb, ROWS, HHH, 3*HHH, 0);
        attn_mma_kernel<<<dim3(BB*NH_, 4), 256>>>(qkvb, qb, ob);
        tgemm<<<dim3(HHH/64, ROWS/64, 4), 128>>>(ob, aw, nullptr, nullptr, p4, ROWS, HHH, HHH, 0);
        ln_add4_kernel<<<ROWS, HHH>>>(x, p4, ab, ln1_g + l*HHH, ln1_b + l*HHH);
        tgemm<<<dim3(FFF/64, ROWS/64, 1), 128>>>(x, w1, b1, nullptr, tmpb, ROWS, HHH, FFF, 1);
        tgemm<<<dim3(HHH/64, ROWS/64, 4), 128>>>(tmpb, w2, nullptr, nullptr, p4, ROWS, FFF, HHH, 0);
        ln_add4_kernel<<<ROWS, HHH>>>(x, p4, b2, ln2_g + l*HHH, ln2_b + l*HHH);
    }

    head_prep_kernel<<<1, HHH>>>(ew, eb, ow1, ob1, u, vv);
    // merged xa/xb head GEMMs: one launch, 400 CTAs (mode 3)
    tgemm<<<dim3(8, ROWS/64, 2), 128>>>(x, ow1, nullptr, nullptr, tmpb, ROWS, HHH, HHH, 3);
    head_kernel<<<dim3(NNN/8, BB), 256>>>(tmpb, tmpb + SLAB, tmpb + 2*SLAB, tmpb + 3*SLAB,
                                          xt, u, vv, ow2, ob2, out);
}

// round 17
// speedup vs baseline: 1.0471x; 1.0471x over previous
#include <cuda_runtime.h>
#include <cuda_fp16.h>
#include <math.h>
#include <stdint.h>

// Problem dims
#define BB   8
#define NNN  200
#define NDD  128
#define HHH  256
#define FFF  1024
#define LLL  3
#define NH_  8
#define DH_  32
#define ROWS (BB*NNN)          // 1600
#define SLAB (ROWS*HHH)        // 409600 floats

// ---------------- scratch (device globals; no allocation allowed) -----------
__device__ float g_x   [ROWS*HHH];
__device__ float g_qkv [ROWS*3*HHH];
__device__ float g_tmp [ROWS*FFF];       // 4 slabs of ROWS*HHH
__device__ float g_o   [ROWS*HHH];
__device__ float g_p4  [4*SLAB];         // split-K=4 GEMM partials
__device__ float g_temb[BB*HHH];
__device__ float g_u   [HHH];
__device__ float g_vv  [HHH];

// ---------------- fp16 helpers ----------------------------------------------
__device__ __forceinline__ uint32_t pack_h2(float a, float b) {
    __half2 h = __floats2half2_rn(a, b);
    return *(uint32_t*)&h;
}
__device__ __forceinline__ void mma_f16(float* c, uint32_t a0, uint32_t a1,
                                        uint32_t a2, uint32_t a3,
                                        uint32_t b0, uint32_t b1) {
    asm volatile(
        "mma.sync.aligned.m16n8k16.row.col.f32.f16.f16.f32 "
        "{%0,%1,%2,%3}, {%4,%5,%6,%7}, {%8,%9}, {%0,%1,%2,%3};"
        : "+f"(c[0]), "+f"(c[1]), "+f"(c[2]), "+f"(c[3])
        : "r"(a0), "r"(a1), "r"(a2), "r"(a3), "r"(b0), "r"(b1));
}

// ------- fp16 GEMM, CTA 64x64, 4 warps of 32x32, BK=32, double-buffered -----
// gridDim.z = split-K; partial z -> C + z*M*Nc (no bias when nz>1).
// mode: 0=+bias, 1=+bias,relu, 2=+bias+temb[row/200],
//       3=dual-W head (bx>>2 selects wa/wb, output slab pair offset)
__global__ void __launch_bounds__(128, 5)
tgemm(const float* __restrict__ A, const float* __restrict__ W,
      const float* __restrict__ bias, const float* __restrict__ temb,
      float* __restrict__ C, int M, int K, int Nc, int mode)
{
    __shared__ __align__(16) uint32_t As[2][64][20];   // 16 u32 = 32 halves/row
    __shared__ __align__(16) uint32_t Bs[2][16][72];   // row=kpair, col=n

    const int tid = threadIdx.x;
    int bx = blockIdx.x;
    const int by = blockIdx.y;
    const int z = blockIdx.z, nz = gridDim.z;
    const int kLen = K / nz;
    const int kstart = z * kLen;

    if (mode == 3) {
        int sel = bx >> 2;
        bx &= 3;
        W += (size_t)sel * HHH * HHH;
        C += (size_t)sel * 2 * M * Nc;   // xa slabs 0,1 ; xb slabs 2,3
    }
    C += (size_t)z * M * Nc;

    const int wid  = tid >> 5, lane = tid & 31;
    const int l4   = lane >> 2, lk = lane & 3;
    const int m0   = (wid >> 1) * 32;     // warp row base (0,32)
    const int n0   = (wid & 1) * 32;      // warp col base (0,32)

    // A staging: row ar, u32 cols ak..ak+7 (k offsets ak*2 .. ak*2+15)
    const int ar = tid >> 1;              // 0..63
    const int ak = (tid & 1) * 8;         // 0 or 8 (k 0 or 16)
    // B staging: kpair rows bk,bk+8, n offset bn
    const int bk = tid >> 4;              // 0..7
    const int bn = (tid & 15) * 4;        // 0..60

    const float* Aptr = A + (size_t)(by*64 + ar)*K + kstart + ak*2;
    const float* Wptr = W + (size_t)kstart*Nc + bx*64 + bn;

    // ---- stage tile 0 ----
    {
        float4 a0v = *(const float4*)(Aptr);
        float4 a1v = *(const float4*)(Aptr + 4);
        float4 a2v = *(const float4*)(Aptr + 8);
        float4 a3v = *(const float4*)(Aptr + 12);
        uint4 pa;
        pa.x = pack_h2(a0v.x, a0v.y); pa.y = pack_h2(a0v.z, a0v.w);
        pa.z = pack_h2(a1v.x, a1v.y); pa.w = pack_h2(a1v.z, a1v.w);
        *(uint4*)&As[0][ar][ak] = pa;
        pa.x = pack_h2(a2v.x, a2v.y); pa.y = pack_h2(a2v.z, a2v.w);
        pa.z = pack_h2(a3v.x, a3v.y); pa.w = pack_h2(a3v.z, a3v.w);
        *(uint4*)&As[0][ar][ak + 4] = pa;
#pragma unroll
        for (int cchunk = 0; cchunk < 2; cchunk++) {
            int kp = bk + cchunk*8;
            const float* w0 = Wptr + (size_t)(2*kp)*Nc;
            float4 x0 = *(const float4*)(w0);
            float4 x1 = *(const float4*)(w0 + Nc);
            uint4 pb;
            pb.x = pack_h2(x0.x, x1.x); pb.y = pack_h2(x0.y, x1.y);
            pb.z = pack_h2(x0.z, x1.z); pb.w = pack_h2(x0.w, x1.w);
            *(uint4*)&Bs[0][kp][bn] = pb;
        }
    }
    __syncthreads();

    float c[2][4][4];
#pragma unroll
    for (int t = 0; t < 2; t++)
#pragma unroll
        for (int f = 0; f < 4; f++)
#pragma unroll
            for (int i = 0; i < 4; i++) c[t][f][i] = 0.f;

    int cur = 0;
#pragma unroll 1
    for (int k0 = 32; k0 < kLen; k0 += 32) {
        // prefetch next tile to registers
        float4 a0v = *(const float4*)(Aptr + k0);
        float4 a1v = *(const float4*)(Aptr + k0 + 4);
        float4 a2v = *(const float4*)(Aptr + k0 + 8);
        float4 a3v = *(const float4*)(Aptr + k0 + 12);
        float4 x0a = *(const float4*)(Wptr + (size_t)(k0 + 2*bk    )*Nc);
        float4 x1a = *(const float4*)(Wptr + (size_t)(k0 + 2*bk + 1)*Nc);
        float4 x0b = *(const float4*)(Wptr + (size_t)(k0 + 2*bk + 16)*Nc);
        float4 x1b = *(const float4*)(Wptr + (size_t)(k0 + 2*bk + 17)*Nc);
        // compute current tile: 2 k16 steps
#pragma unroll
        for (int s = 0; s < 2; s++) {
            const int s8 = s * 8;
            uint32_t a[2][4];
#pragma unroll
            for (int t = 0; t < 2; t++) {
                const int mt = m0 + t*16;
                a[t][0] = As[cur][mt + l4    ][s8 + lk    ];
                a[t][1] = As[cur][mt + 8 + l4][s8 + lk    ];
                a[t][2] = As[cur][mt + l4    ][s8 + lk + 4];
                a[t][3] = As[cur][mt + 8 + l4][s8 + lk + 4];
            }
#pragma unroll
            for (int f = 0; f < 4; f++) {
                uint32_t b0 = Bs[cur][s8 + lk    ][n0 + f*8 + l4];
                uint32_t b1 = Bs[cur][s8 + lk + 4][n0 + f*8 + l4];
                mma_f16(c[0][f], a[0][0], a[0][1], a[0][2], a[0][3], b0, b1);
                mma_f16(c[1][f], a[1][0], a[1][1], a[1][2], a[1][3], b0, b1);
            }
        }
        int nb = cur ^ 1;
        {
            uint4 pa;
            pa.x = pack_h2(a0v.x, a0v.y); pa.y = pack_h2(a0v.z, a0v.w);
            pa.z = pack_h2(a1v.x, a1v.y); pa.w = pack_h2(a1v.z, a1v.w);
            *(uint4*)&As[nb][ar][ak] = pa;
            pa.x = pack_h2(a2v.x, a2v.y); pa.y = pack_h2(a2v.z, a2v.w);
            pa.z = pack_h2(a3v.x, a3v.y); pa.w = pack_h2(a3v.z, a3v.w);
            *(uint4*)&As[nb][ar][ak + 4] = pa;
            uint4 pb;
            pb.x = pack_h2(x0a.x, x1a.x); pb.y = pack_h2(x0a.y, x1a.y);
            pb.z = pack_h2(x0a.z, x1a.z); pb.w = pack_h2(x0a.w, x1a.w);
            *(uint4*)&Bs[nb][bk][bn] = pb;
            pb.x = pack_h2(x0b.x, x1b.x); pb.y = pack_h2(x0b.y, x1b.y);
            pb.z = pack_h2(x0b.z, x1b.z); pb.w = pack_h2(x0b.w, x1b.w);
            *(uint4*)&Bs[nb][bk + 8][bn] = pb;
        }
        __syncthreads();
        cur = nb;
    }
    // ---- last tile ----
#pragma unroll
    for (int s = 0; s < 2; s++) {
        const int s8 = s * 8;
        uint32_t a[2][4];
#pragma unroll
        for (int t = 0; t < 2; t++) {
            const int mt = m0 + t*16;
            a[t][0] = As[cur][mt + l4    ][s8 + lk    ];
            a[t][1] = As[cur][mt + 8 + l4][s8 + lk    ];
            a[t][2] = As[cur][mt + l4    ][s8 + lk + 4];
            a[t][3] = As[cur][mt + 8 + l4][s8 + lk + 4];
        }
#pragma unroll
        for (int f = 0; f < 4; f++) {
            uint32_t b0 = Bs[cur][s8 + lk    ][n0 + f*8 + l4];
            uint32_t b1 = Bs[cur][s8 + lk + 4][n0 + f*8 + l4];
            mma_f16(c[0][f], a[0][0], a[0][1], a[0][2], a[0][3], b0, b1);
            mma_f16(c[1][f], a[1][0], a[1][1], a[1][2], a[1][3], b0, b1);
        }
    }

    // epilogue: warp rows m0+16t+l4(+8), cols n0+f*8+lk*2 (+1)
#pragma unroll
    for (int t = 0; t < 2; t++) {
#pragma unroll
        for (int f = 0; f < 4; f++) {
            const int col = bx*64 + n0 + f*8 + lk*2;
            float bx0 = 0.f, bx1 = 0.f;
            if (nz == 1 && bias) {
                float2 bv = *(const float2*)(bias + col);
                bx0 = bv.x; bx1 = bv.y;
            }
#pragma unroll
            for (int hh = 0; hh < 2; hh++) {
                const int row = by*64 + m0 + t*16 + l4 + hh*8;
                float v0 = c[t][f][hh*2+0] + bx0;
                float v1 = c[t][f][hh*2+1] + bx1;
                if (mode == 1) { v0 = fmaxf(v0, 0.f); v1 = fmaxf(v1, 0.f); }
                else if (mode == 2) {
                    int b = row / NNN;
                    float2 tv = *(const float2*)(temb + b*HHH + col);
                    v0 += tv.x; v1 += tv.y;
                }
                *(float2*)(C + (size_t)row*Nc + col) = make_float2(v0, v1);
            }
        }
    }
}

// ---------------- t embedding -----------------------------------------------
__global__ void temb_kernel(const float* __restrict__ t, const float* __restrict__ tw1,
                            const float* __restrict__ tb1, const float* __restrict__ tw2,
                            const float* __restrict__ tb2, float* __restrict__ temb)
{
    __shared__ float s[HHH];
    int b = blockIdx.x, h = threadIdx.x;
    float pre = t[b]*tw1[h] + tb1[h];
    s[h] = pre / (1.f + __expf(-pre));
    __syncthreads();
    float acc = tb2[h];
    for (int c = 0; c < HHH; c++) acc = fmaf(s[c], tw2[c*HHH + h], acc);
    temb[b*HHH + h] = acc;
}

// ---------------- fp16 tensor-core attention, warp-split keys ----------------
// grid (64 bh, 4 qtile of 64), 256 threads / 8 warps.
// Warp w: m-tile (w&3)*16, key-half w>>2. S = Q@K^T via m16n8k16 f16; exp in
// regs; S C-frag == P A-frag -> O=P@V with no smem P. Upper warp group's
// partials combine via smem. No-max softmax. Padded keys 200..207 zeroed.
__global__ void __launch_bounds__(256, 2)
attn_mma_kernel(const float* __restrict__ qkv, float* __restrict__ o)
{
    __shared__ uint32_t Qs[64][20];    // 32 halves/row = 16 u32 + pad
    __shared__ uint32_t Ksm[208][20];
    __shared__ uint32_t Vt[32][108];   // transposed: [dim][key-pairs]
    __shared__ float cbuf[4][32][18];  // partial combine: oacc[16], rs0, rs2

    const int bh = blockIdx.x;
    const int b = bh >> 3, h = bh & 7;
    const int qt = blockIdx.y;
    const int tid = threadIdx.x;
    const int w = tid >> 5, lane = tid & 31;
    const int l4 = lane >> 2, lk = lane & 3;
    const int w16 = (w & 3) * 16;
    const int kh = w >> 2;

    // Q tile: scaled, fp16, zero-padded rows
    for (int idx = tid; idx < 64*8; idx += 256) {
        int r = idx >> 3, g4 = idx & 7;
        int i = qt*64 + r;
        float4 v = make_float4(0.f, 0.f, 0.f, 0.f);
        if (i < NNN) v = *(const float4*)(qkv + (size_t)(b*NNN + i)*768 + h*32 + g4*4);
        const float sc = 0.17677669529663687f;  // 1/sqrt(32)
        Qs[r][g4*2    ] = pack_h2(v.x*sc, v.y*sc);
        Qs[r][g4*2 + 1] = pack_h2(v.z*sc, v.w*sc);
    }
    // K (fp16), zero rows >= 200
    for (int idx = tid; idx < 208*8; idx += 256) {
        int j = idx >> 3, g4 = idx & 7;
        float4 v = make_float4(0.f, 0.f, 0.f, 0.f);
        if (j < NNN) v = *(const float4*)(qkv + (size_t)(b*NNN + j)*768 + h*32 + 256 + g4*4);
        Ksm[j][g4*2    ] = pack_h2(v.x, v.y);
        Ksm[j][g4*2 + 1] = pack_h2(v.z, v.w);
    }
    // V transposed (fp16 halves along key dim), zero rows >= 200
    for (int idx = tid; idx < 208*8; idx += 256) {
        int j = idx >> 3, g4 = idx & 7;
        float4 v = make_float4(0.f, 0.f, 0.f, 0.f);
        if (j < NNN) v = *(const float4*)(qkv + (size_t)(b*NNN + j)*768 + h*32 + 512 + g4*4);
        __half* r0 = (__half*)&Vt[g4*4    ][0];
        __half* r1 = (__half*)&Vt[g4*4 + 1][0];
        __half* r2 = (__half*)&Vt[g4*4 + 2][0];
        __half* r3 = (__half*)&Vt[g4*4 + 3][0];
        r0[j] = __float2half_rn(v.x);
        r1[j] = __float2half_rn(v.y);
        r2[j] = __float2half_rn(v.z);
        r3[j] = __float2half_rn(v.w);
    }
    __syncthreads();

    // Q fragments (2 k-steps of 16 halves), register-resident
    uint32_t qa[2][4];
#pragma unroll
    for (int s = 0; s < 2; s++) {
        const int o8 = s*8;
        qa[s][0] = Qs[w16 + l4    ][o8 + lk    ];
        qa[s][1] = Qs[w16 + 8 + l4][o8 + lk    ];
        qa[s][2] = Qs[w16 + l4    ][o8 + lk + 4];
        qa[s][3] = Qs[w16 + 8 + l4][o8 + lk + 4];
    }

    float oacc[4][4];
#pragma unroll
    for (int f = 0; f < 4; f++)
#pragma unroll
        for (int i = 0; i < 4; i++) oacc[f][i] = 0.f;
    float rs0 = 0.f, rs2 = 0.f;

    const int fbeg = kh ? 7 : 0;
    const int fend = kh ? 13 : 7;
#pragma unroll 1
    for (int f = fbeg; f < fend; f++) {     // key blocks of 16
        const int klo = 16*f + l4;
        float clo[4] = {0.f, 0.f, 0.f, 0.f};
        float chi[4] = {0.f, 0.f, 0.f, 0.f};
#pragma unroll
        for (int s = 0; s < 2; s++) {
            const int o8 = s*8;
            uint32_t b0 = Ksm[klo    ][o8 + lk];
            uint32_t b1 = Ksm[klo    ][o8 + lk + 4];
            mma_f16(clo, qa[s][0], qa[s][1], qa[s][2], qa[s][3], b0, b1);
            uint32_t c0 = Ksm[klo + 8][o8 + lk];
            uint32_t c1 = Ksm[klo + 8][o8 + lk + 4];
            mma_f16(chi, qa[s][0], qa[s][1], qa[s][2], qa[s][3], c0, c1);
        }
        float p0 = __expf(clo[0]), p1 = __expf(clo[1]);
        float p2 = __expf(clo[2]), p3 = __expf(clo[3]);
        float p4, p5, p6, p7;
        if (f == 12) { p4 = p5 = p6 = p7 = 0.f; }   // keys 200..207 padded
        else {
            p4 = __expf(chi[0]); p5 = __expf(chi[1]);
            p6 = __expf(chi[2]); p7 = __expf(chi[3]);
        }
        // row sums across the quad (lanes sharing l4)
        float s01 = (p0 + p1) + (p4 + p5);
        float s23 = (p2 + p3) + (p6 + p7);
        s01 += __shfl_xor_sync(0xffffffffu, s01, 1);
        s01 += __shfl_xor_sync(0xffffffffu, s01, 2);
        s23 += __shfl_xor_sync(0xffffffffu, s23, 1);
        s23 += __shfl_xor_sync(0xffffffffu, s23, 2);
        rs0 += s01; rs2 += s23;
        // P fragment = packed exps (C-frag layout == A-frag layout)
        uint32_t a0 = pack_h2(p0, p1);
        uint32_t a1 = pack_h2(p2, p3);
        uint32_t a2 = pack_h2(p4, p5);
        uint32_t a3 = pack_h2(p6, p7);
#pragma unroll
        for (int f2 = 0; f2 < 4; f2++) {
            uint32_t b0 = Vt[f2*8 + l4][8*f + lk    ];
            uint32_t b1 = Vt[f2*8 + l4][8*f + lk + 4];
            mma_f16(oacc[f2], a0, a1, a2, a3, b0, b1);
        }
    }

    // upper warp group publishes partials
    if (w >= 4) {
        float* dst = &cbuf[w - 4][lane][0];
#pragma unroll
        for (int f2 = 0; f2 < 4; f2++)
#pragma unroll
            for (int i = 0; i < 4; i++) dst[f2*4 + i] = oacc[f2][i];
        dst[16] = rs0; dst[17] = rs2;
    }
    __syncthreads();
    if (w < 4) {
        const float* src = &cbuf[w][lane][0];
#pragma unroll
        for (int f2 = 0; f2 < 4; f2++)
#pragma unroll
            for (int i = 0; i < 4; i++) oacc[f2][i] += src[f2*4 + i];
        rs0 += src[16]; rs2 += src[17];

        const float inv0 = 1.f / rs0;
        const float inv2 = 1.f / rs2;
        const int i0 = qt*64 + w16 + l4;
        const int i2 = i0 + 8;
#pragma unroll
        for (int f2 = 0; f2 < 4; f2++) {
            const int col = h*32 + f2*8 + 2*lk;
            if (i0 < NNN)
                *(float2*)(o + (size_t)(b*NNN + i0)*HHH + col) =
                    make_float2(oacc[f2][0]*inv0, oacc[f2][1]*inv0);
            if (i2 < NNN)
                *(float2*)(o + (size_t)(b*NNN + i2)*HHH + col) =
                    make_float2(oacc[f2][2]*inv2, oacc[f2][3]*inv2);
        }
    }
}

// -------- LN(x + p0..p3 + bias) in place: merges split-K=4 partials ---------
__global__ void ln_add4_kernel(float* __restrict__ x, const float* __restrict__ p,
                               const float* __restrict__ bias,
                               const float* __restrict__ g, const float* __restrict__ b)
{
    int row = blockIdx.x, c = threadIdx.x;
    size_t idx = (size_t)row*HHH + c;
    float v = x[idx] + (p[idx] + p[SLAB + idx]) + (p[2*(size_t)SLAB + idx] + p[3*(size_t)SLAB + idx]) + bias[c];
    float s1 = v, s2 = v*v;
#pragma unroll
    for (int o = 16; o; o >>= 1) {
        s1 += __shfl_xor_sync(0xffffffffu, s1, o);
        s2 += __shfl_xor_sync(0xffffffffu, s2, o);
    }
    __shared__ float a1[8], a2[8];
    int w = c >> 5, lane = c & 31;
    if (lane == 0) { a1[w] = s1; a2[w] = s2; }
    __syncthreads();
    float t1 = 0.f, t2 = 0.f;
#pragma unroll
    for (int k = 0; k < 8; k++) { t1 += a1[k]; t2 += a2[k]; }
    float mean = t1 * (1.f/256.f);
    float var  = t2 * (1.f/256.f) - mean*mean;
    float inv  = rsqrtf(var + 1e-5f);
    x[idx] = (v - mean)*inv*g[c] + b[c];
}

// ---------------- head precompute: u = ew @ wc, v = eb @ wc + ob1 ----------
__global__ void head_prep_kernel(const float* __restrict__ ew, const float* __restrict__ eb,
                                 const float* __restrict__ ow1, const float* __restrict__ ob1,
                                 float* __restrict__ u, float* __restrict__ v)
{
    int d = threadIdx.x;
    const float* wc = ow1 + 512*HHH;
    float su = 0.f, sv = 0.f;
    for (int c = 0; c < HHH; c++) {
        float w = wc[c*HHH + d];
        su = fmaf(ew[c], w, su);
        sv = fmaf(eb[c], w, sv);
    }
    u[d] = su;
    v[d] = sv + ob1[d];
}

// ---------------- pairwise head ---------------------------------------------
__global__ void head_kernel(const float* __restrict__ xa0, const float* __restrict__ xa1,
                            const float* __restrict__ xb0, const float* __restrict__ xb1,
                            const float* __restrict__ xt, const float* __restrict__ u,
                            const float* __restrict__ v, const float* __restrict__ ow2,
                            const float* __restrict__ ob2, float* __restrict__ out)
{
    __shared__ float xa_s[8][257];
    __shared__ float xb_s[32][257];
    __shared__ float us[HHH];
    __shared__ float2 w2s[HHH];
    const int b = blockIdx.y;
    const int i0 = blockIdx.x * 8;
    const int tid = threadIdx.x;
    const int ii = tid >> 5, jj = tid & 31;

    for (int idx = tid; idx < 8*HHH; idx += 256) {
        int r = idx >> 8, c = idx & 255;
        size_t g = (size_t)(b*NNN + i0 + r)*HHH + c;
        xa_s[r][c] = xa0[g] + xa1[g] + v[c];
    }
    us[tid] = u[tid];
    w2s[tid] = make_float2(ow2[tid*2], ow2[tid*2 + 1]);
    const float obv0 = ob2[0], obv1 = ob2[1];

    for (int j0 = 0; j0 < NNN; j0 += 32) {
        __syncthreads();
        for (int idx = tid; idx < 32*HHH; idx += 256) {
            int r = idx >> 8, c = idx & 255;
            if (j0 + r < NNN) {
                size_t g = (size_t)(b*NNN + j0 + r)*HHH + c;
                xb_s[r][c] = xb0[g] + xb1[g];
            }
        }
        __syncthreads();
        int i = i0 + ii, j = j0 + jj;
        if (j < NNN) {
            float xtv = xt[(size_t)(b*NNN + i)*NNN + j];
            float a0 = 0.f, a1 = 0.f;
#pragma unroll 4
            for (int c = 0; c < HHH; c++) {
                float pre = xa_s[ii][c] + fmaf(xtv, us[c], xb_s[jj][c]);
                float sv2 = __fdividef(pre, 1.f + __expf(-pre));
                float2 w = w2s[c];
                a0 = fmaf(sv2, w.x, a0);
                a1 = fmaf(sv2, w.y, a1);
            }
            ((float2*)out)[(size_t)(b*NNN + i)*NNN + j] = make_float2(a0 + obv0, a1 + obv1);
        }
    }
}

// ---------------- host orchestration ----------------------------------------
extern "C" void kernel_launch(void* const* d_in, const int* in_sizes, int n_in,
                              void* d_out, int out_size)
{
    const float* h_in  = (const float*)d_in[0];
    const float* xt    = (const float*)d_in[1];
    const float* t     = (const float*)d_in[2];
    const float* tw1   = (const float*)d_in[3];
    const float* tb1   = (const float*)d_in[4];
    const float* tw2   = (const float*)d_in[5];
    const float* tb2   = (const float*)d_in[6];
    const float* ew    = (const float*)d_in[7];
    const float* eb    = (const float*)d_in[8];
    const float* pw    = (const float*)d_in[9];
    const float* pb    = (const float*)d_in[10];
    const float* qkv_w = (const float*)d_in[11];
    const float* qkv_b = (const float*)d_in[12];
    const float* ao_w  = (const float*)d_in[13];
    const float* ao_b  = (const float*)d_in[14];
    const float* ln1_g = (const float*)d_in[15];
    const float* ln1_b = (const float*)d_in[16];
    const float* f1_w  = (const float*)d_in[17];
    const float* f1_b  = (const float*)d_in[18];
    const float* f2_w  = (const float*)d_in[19];
    const float* f2_b  = (const float*)d_in[20];
    const float* ln2_g = (const float*)d_in[21];
    const float* ln2_b = (const float*)d_in[22];
    const float* ow1   = (const float*)d_in[23];
    const float* ob1   = (const float*)d_in[24];
    const float* ow2   = (const float*)d_in[25];
    const float* ob2   = (const float*)d_in[26];
    float* out = (float*)d_out;

    float *x, *qkvb, *tmpb, *ob, *p4, *temb, *u, *vv;
    cudaGetSymbolAddress((void**)&x,    g_x);
    cudaGetSymbolAddress((void**)&qkvb, g_qkv);
    cudaGetSymbolAddress((void**)&tmpb, g_tmp);
    cudaGetSymbolAddress((void**)&ob,   g_o);
    cudaGetSymbolAddress((void**)&p4,   g_p4);
    cudaGetSymbolAddress((void**)&temb, g_temb);
    cudaGetSymbolAddress((void**)&u,    g_u);
    cudaGetSymbolAddress((void**)&vv,   g_vv);

    temb_kernel<<<BB, HHH>>>(t, tw1, tb1, tw2, tb2, temb);
    tgemm<<<dim3(HHH/64, ROWS/64, 1), 128>>>(h_in, pw, pb, temb, x, ROWS, NDD, HHH, 2);

    for (int l = 0; l < LLL; l++) {
        const float* qw = qkv_w + (size_t)l*HHH*3*HHH;
        const float* qb = qkv_b + l*3*HHH;
        const float* aw = ao_w + (size_t)l*HHH*HHH;
        const float* ab = ao_b + l*HHH;
        const float* w1 = f1_w + (size_t)l*HHH*FFF;
        const float* b1 = f1_b + l*FFF;
        const float* w2 = f2_w + (size_t)l*FFF*HHH;
        const float* b2 = f2_b + l*HHH;

        tgemm<<<dim3(3*HHH/64, ROWS/64, 1), 128>>>(x, qw, qb, nullptr, qkvb, ROWS, HHH, 3*HHH, 0);
        attn_mma_kernel<<<dim3(BB*NH_, 4), 256>>>(qkvb, ob);
        tgemm<<<dim3(HHH/64, ROWS/64, 4), 128>>>(ob, aw, nullptr, nullptr, p4, ROWS, HHH, HHH, 0);
        ln_add4_kernel<<<ROWS, HHH>>>(x, p4, ab, ln1_g + l*HHH, ln1_b + l*HHH);
        tgemm<<<dim3(FFF/64, ROWS/64, 1), 128>>>(x, w1, b1, nullptr, tmpb, ROWS, HHH, FFF, 1);
        tgemm<<<dim3(HHH/64, ROWS/64, 4), 128>>>(tmpb, w2, nullptr, nullptr, p4, ROWS, FFF, HHH, 0);
        ln_add4_kernel<<<ROWS, HHH>>>(x, p4, b2, ln2_g + l*HHH, ln2_b + l*HHH);
    }

    head_prep_kernel<<<1, HHH>>>(ew, eb, ow1, ob1, u, vv);
    // merged xa/xb head GEMMs: one launch, 400 CTAs (mode 3)
    tgemm<<<dim3(8, ROWS/64, 2), 128>>>(x, ow1, nullptr, nullptr, tmpb, ROWS, HHH, HHH, 3);
    head_kernel<<<dim3(NNN/8, BB), 256>>>(tmpb, tmpb + SLAB, tmpb + 2*SLAB, tmpb + 3*SLAB,
                                          xt, u, vv, ow2, ob2, out);
}